// round 12
// baseline (speedup 1.0000x reference)
#include <cuda_runtime.h>
#include <cuda_bf16.h>
#include <math.h>
#include <stdint.h>

// ---------------- problem constants ----------------
#define BATCH   2
#define SEQLEN  1024
#define DMODEL  1024
#define DINNER  2048
#define DSTATE  16
#define DTRANK  64
#define MTOT    (BATCH*SEQLEN)        // 2048 rows (b*L + l)
#define NXPROJ  96
#define NXP128  128                   // padded x_dbl row stride

// ---------------- scratch (device globals; no allocation) ----------------
__device__ float g_xz   [MTOT * 2*DINNER];  // [m, 4096]  x | z
__device__ float g_u    [MTOT * DINNER];    // [m, d]     conv+silu output
__device__ float g_uT   [BATCH * DINNER * SEQLEN]; // [(b*2048+d), l]
__device__ float g_xdbl [MTOT * NXP128];    // [m, 128]   dt_low | B | C | pad
__device__ float g_xpart[8 * MTOT * NXP128];// split-K fp32 partials
__device__ float g_bc   [MTOT * 32];        // [m][2n]=B_n, [2n+1]=C_n (L2-hot)
__device__ float g_dT   [BATCH * DINNER * SEQLEN]; // delta transposed
__device__ float g_yT   [BATCH * DINNER * SEQLEN]; // scan output [(b*2048+d), l]

// split-bf16 operands (row-major hi / lo)
__device__ __nv_bfloat16 g_hsH  [MTOT * DMODEL],      g_hsL  [MTOT * DMODEL];
__device__ __nv_bfloat16 g_inWH [2*DINNER * DMODEL],  g_inWL [2*DINNER * DMODEL];
__device__ __nv_bfloat16 g_uH   [MTOT * DINNER],      g_uL   [MTOT * DINNER];
__device__ __nv_bfloat16 g_xpWH [128 * DINNER],       g_xpWL [128 * DINNER];  // rows 96..127 stay zero
__device__ __nv_bfloat16 g_y2H  [MTOT * DINNER],      g_y2L  [MTOT * DINNER];
__device__ __nv_bfloat16 g_outWH[DMODEL * DINNER],    g_outWL[DMODEL * DINNER];

__device__ __forceinline__ float siluf(float x) { return x / (1.f + __expf(-x)); }

// ================= mma helpers (sm_80-compatible PTX) =================
#define MMA_BF16(d, a, b)                                                     \
    asm volatile("mma.sync.aligned.m16n8k16.row.col.f32.bf16.bf16.f32 "       \
        "{%0,%1,%2,%3}, {%4,%5,%6,%7}, {%8,%9}, {%0,%1,%2,%3};"               \
        : "+f"((d)[0]), "+f"((d)[1]), "+f"((d)[2]), "+f"((d)[3])              \
        : "r"((a)[0]), "r"((a)[1]), "r"((a)[2]), "r"((a)[3]),                 \
          "r"((b)[0]), "r"((b)[1]))

#define LDSM4(r, addr)                                                        \
    asm volatile("ldmatrix.sync.aligned.m8n8.x4.shared.b16 {%0,%1,%2,%3}, [%4];" \
        : "=r"((r)[0]), "=r"((r)[1]), "=r"((r)[2]), "=r"((r)[3]) : "r"(addr))

#define CP_ASYNC16(s, g)                                                      \
    asm volatile("cp.async.cg.shared.global [%0], [%1], 16;" :: "r"(s), "l"(g))

// byte offset in a [rows x 32 bf16] tile with XOR swizzle (conflict-free)
__device__ __forceinline__ uint32_t swz(int r, int c) {
    return (uint32_t)(r * 64 + ((c ^ ((r >> 1) & 3)) << 4));
}

// ---------------- merged split: fp32 -> (hi,lo) bf16 for 4 tensors ----------------
#define N4_HS   (MTOT * DMODEL / 4)
#define N4_INW  (2 * DINNER * DMODEL / 4)
#define N4_OUTW (DMODEL * DINNER / 4)
#define N4_XW   (NXPROJ * DINNER / 4)
__global__ void split4_kernel(const float* __restrict__ s0, __nv_bfloat16* __restrict__ h0, __nv_bfloat16* __restrict__ l0,
                              const float* __restrict__ s1, __nv_bfloat16* __restrict__ h1, __nv_bfloat16* __restrict__ l1,
                              const float* __restrict__ s2, __nv_bfloat16* __restrict__ h2, __nv_bfloat16* __restrict__ l2,
                              const float* __restrict__ s3, __nv_bfloat16* __restrict__ h3, __nv_bfloat16* __restrict__ l3)
{
    int idx = blockIdx.x * blockDim.x + threadIdx.x;   // float4 index
    if (idx >= N4_HS + N4_INW + N4_OUTW + N4_XW) return;
    const float* s; __nv_bfloat16 *hp, *lp;
    if (idx < N4_HS)                          { s = s0; hp = h0; lp = l0; }
    else if (idx < N4_HS + N4_INW)            { idx -= N4_HS; s = s1; hp = h1; lp = l1; }
    else if (idx < N4_HS + N4_INW + N4_OUTW)  { idx -= N4_HS + N4_INW; s = s2; hp = h2; lp = l2; }
    else                                      { idx -= N4_HS + N4_INW + N4_OUTW; s = s3; hp = h3; lp = l3; }
    float4 v = ((const float4*)s)[idx];
    float f[4] = {v.x, v.y, v.z, v.w};
    union { __nv_bfloat16 h[4]; uint2 u; } H, L;
#pragma unroll
    for (int i = 0; i < 4; i++) {
        __nv_bfloat16 hh = __float2bfloat16(f[i]);
        H.h[i] = hh;
        L.h[i] = __float2bfloat16(f[i] - __bfloat162float(hh));
    }
    ((uint2*)hp)[idx] = H.u;
    ((uint2*)lp)[idx] = L.u;
}

// ---------------- BIG: 3-term split-bf16 MMA GEMM, CTA 128x128, warp tile 64x32 ----------------
// 8 warps (2m x 4n). Per BK=32: 24 LDSM4 for 96 HMMA (4:1 ratio, B frags amortized over 4 m-frags).
__global__ __launch_bounds__(256, 2) void mma_gemm_big(
    const __nv_bfloat16* __restrict__ Ah, const __nv_bfloat16* __restrict__ Al,
    const __nv_bfloat16* __restrict__ Bh, const __nv_bfloat16* __restrict__ Bl,
    float* __restrict__ C, int N, int K)
{
    constexpr int MATB   = 128 * 64;          // 8192 B per matrix tile (128 rows x 32 bf16)
    constexpr int STAGEB = 4 * MATB;          // Ah | Al | Bh | Bl = 32768

    extern __shared__ __align__(128) char smem[];
    const uint32_t sb = (uint32_t)__cvta_generic_to_shared(smem);
    const int tid = threadIdx.x, lane = tid & 31, wid = tid >> 5;
    const int wm = wid >> 2, wn = wid & 3;              // 2 x 4 warps
    const int m0 = blockIdx.y * 128, n0 = blockIdx.x * 128;
    const int KT = K >> 5;

    const __nv_bfloat16* gAh = Ah + (size_t)m0 * K;
    const __nv_bfloat16* gAl = Al + (size_t)m0 * K;
    const __nv_bfloat16* gBh = Bh + (size_t)n0 * K;
    const __nv_bfloat16* gBl = Bl + (size_t)n0 * K;

    const int cr = tid >> 1, cc = (tid & 1) * 2;        // 2 chunks/thread/matrix

    float acc[4][4][4];
#pragma unroll
    for (int i = 0; i < 4; i++)
#pragma unroll
        for (int j = 0; j < 4; j++)
#pragma unroll
            for (int q = 0; q < 4; q++) acc[i][j][q] = 0.f;

    auto load_tile = [&](int ktIdx, int stage) {
        const int kO = ktIdx * 32;
        const uint32_t sB = sb + stage * STAGEB;
        CP_ASYNC16(sB + swz(cr, cc),              gAh + (size_t)cr * K + kO + cc * 8);
        CP_ASYNC16(sB + swz(cr, cc + 1),          gAh + (size_t)cr * K + kO + cc * 8 + 8);
        CP_ASYNC16(sB + MATB + swz(cr, cc),       gAl + (size_t)cr * K + kO + cc * 8);
        CP_ASYNC16(sB + MATB + swz(cr, cc + 1),   gAl + (size_t)cr * K + kO + cc * 8 + 8);
        CP_ASYNC16(sB + 2 * MATB + swz(cr, cc),     gBh + (size_t)cr * K + kO + cc * 8);
        CP_ASYNC16(sB + 2 * MATB + swz(cr, cc + 1), gBh + (size_t)cr * K + kO + cc * 8 + 8);
        CP_ASYNC16(sB + 3 * MATB + swz(cr, cc),     gBl + (size_t)cr * K + kO + cc * 8);
        CP_ASYNC16(sB + 3 * MATB + swz(cr, cc + 1), gBl + (size_t)cr * K + kO + cc * 8 + 8);
        asm volatile("cp.async.commit_group;" ::: "memory");
    };

    load_tile(0, 0);
    load_tile(1, 1);

    const int arow = wm * 64 + (lane & 15);             // +mt*16, q invariant under +16
    const int achb = lane >> 4;
    const int qA   = (arow >> 1) & 3;
    const int brow = wn * 32 + (lane & 7) + ((lane >> 4) << 3);   // +p*16
    const int bchb = (lane >> 3) & 1;
    const int qB   = (brow >> 1) & 3;

    int stage = 0;
    for (int kt = 0; kt < KT; kt++) {
        asm volatile("cp.async.wait_group 1;" ::: "memory");
        __syncthreads();
        if (kt + 2 < KT) {
            int ns = stage + 2; if (ns >= 3) ns -= 3;
            load_tile(kt + 2, ns);
        }
        const uint32_t base = sb + stage * STAGEB;
#pragma unroll
        for (int ks = 0; ks < 2; ks++) {
            uint32_t aH[4][4], aL[4][4];
            const uint32_t acoff = (uint32_t)(((ks * 2 + achb) ^ qA) << 4);
#pragma unroll
            for (int mt = 0; mt < 4; mt++) {
                LDSM4(aH[mt], base + (uint32_t)((arow + mt * 16) * 64) + acoff);
                LDSM4(aL[mt], base + MATB + (uint32_t)((arow + mt * 16) * 64) + acoff);
            }
            const uint32_t bcoff = (uint32_t)(((ks * 2 + bchb) ^ qB) << 4);
#pragma unroll
            for (int p = 0; p < 2; p++) {
                uint32_t bh[4], bl[4];
                LDSM4(bh, base + 2 * MATB + (uint32_t)((brow + p * 16) * 64) + bcoff);
                LDSM4(bl, base + 3 * MATB + (uint32_t)((brow + p * 16) * 64) + bcoff);
#pragma unroll
                for (int mt = 0; mt < 4; mt++) {
                    MMA_BF16(acc[mt][2 * p],     aH[mt], bh);
                    MMA_BF16(acc[mt][2 * p],     aL[mt], bh);
                    MMA_BF16(acc[mt][2 * p],     aH[mt], bl);
                    MMA_BF16(acc[mt][2 * p + 1], aH[mt], bh + 2);
                    MMA_BF16(acc[mt][2 * p + 1], aL[mt], bh + 2);
                    MMA_BF16(acc[mt][2 * p + 1], aH[mt], bl + 2);
                }
            }
        }
        if (++stage == 3) stage = 0;
    }

    // epilogue: warp tile 64x32
#pragma unroll
    for (int mt = 0; mt < 4; mt++) {
        const int row = m0 + wm * 64 + mt * 16 + (lane >> 2);
#pragma unroll
        for (int nt = 0; nt < 4; nt++) {
            const int col = n0 + wn * 32 + nt * 8 + (lane & 3) * 2;
            *(float2*)&C[(size_t)row * N + col] =
                make_float2(acc[mt][nt][0], acc[mt][nt][1]);
            *(float2*)&C[(size_t)(row + 8) * N + col] =
                make_float2(acc[mt][nt][2], acc[mt][nt][3]);
        }
    }
}
#define GEMMBIG_SMEM (3 * 4 * 128 * 64)   // 98304

// ---------------- 64-wide GEMM (unchanged): CTA 128x64, split-K via blockIdx.z ----------------
__global__ __launch_bounds__(256, 2) void mma_gemm64(
    const __nv_bfloat16* __restrict__ Ah, const __nv_bfloat16* __restrict__ Al,
    const __nv_bfloat16* __restrict__ Bh, const __nv_bfloat16* __restrict__ Bl,
    float* __restrict__ C, int N, int K, int kLen)
{
    constexpr int BN     = 64;
    constexpr int NT     = BN / 16;           // 4
    constexpr int AMATB  = 128 * 64;          // 8192
    constexpr int BMATB  = BN * 64;           // 4096
    constexpr int STAGEB = 2 * AMATB + 2 * BMATB;   // 24576

    extern __shared__ __align__(128) char smem[];
    const uint32_t sb = (uint32_t)__cvta_generic_to_shared(smem);
    const int tid = threadIdx.x, lane = tid & 31, wid = tid >> 5;
    const int wm = wid >> 1, wn = wid & 1;
    const int m0 = blockIdx.y * 128, n0 = blockIdx.x * BN;
    const int KT = kLen >> 5;
    const int kBase = blockIdx.z * kLen;
    C += (size_t)blockIdx.z * (size_t)(gridDim.y * 128) * N;

    const __nv_bfloat16* gAh = Ah + (size_t)m0 * K + kBase;
    const __nv_bfloat16* gAl = Al + (size_t)m0 * K + kBase;
    const __nv_bfloat16* gBh = Bh + (size_t)n0 * K + kBase;
    const __nv_bfloat16* gBl = Bl + (size_t)n0 * K + kBase;

    const int ar = tid >> 1, ac = (tid & 1) * 2;
    const int br = tid >> 2, bc = tid & 3;

    float acc[2][NT][4];
#pragma unroll
    for (int i = 0; i < 2; i++)
#pragma unroll
        for (int j = 0; j < NT; j++)
#pragma unroll
            for (int q = 0; q < 4; q++) acc[i][j][q] = 0.f;

    auto load_tile = [&](int ktIdx, int stage) {
        const int kO = ktIdx * 32;
        const uint32_t sB = sb + stage * STAGEB;
        CP_ASYNC16(sB + swz(ar, ac),             gAh + (size_t)ar * K + kO + ac * 8);
        CP_ASYNC16(sB + swz(ar, ac + 1),         gAh + (size_t)ar * K + kO + ac * 8 + 8);
        CP_ASYNC16(sB + AMATB + swz(ar, ac),     gAl + (size_t)ar * K + kO + ac * 8);
        CP_ASYNC16(sB + AMATB + swz(ar, ac + 1), gAl + (size_t)ar * K + kO + ac * 8 + 8);
        CP_ASYNC16(sB + 2 * AMATB + swz(br, bc),         gBh + (size_t)br * K + kO + bc * 8);
        CP_ASYNC16(sB + 2 * AMATB + BMATB + swz(br, bc), gBl + (size_t)br * K + kO + bc * 8);
        asm volatile("cp.async.commit_group;" ::: "memory");
    };

    load_tile(0, 0);
    load_tile(1, 1);

    const int arow  = wm * 32 + (lane & 15);
    const int achb  = lane >> 4;
    const int qA    = (arow >> 1) & 3;
    const int brow  = wn * (BN / 2) + (lane & 7) + ((lane >> 4) << 3);
    const int bchb  = (lane >> 3) & 1;
    const int qB    = (brow >> 1) & 3;

    int stage = 0;
    for (int kt = 0; kt < KT; kt++) {
        asm volatile("cp.async.wait_group 1;" ::: "memory");
        __syncthreads();
        if (kt + 2 < KT) {
            int ns = stage + 2; if (ns >= 3) ns -= 3;
            load_tile(kt + 2, ns);
        }
        const uint32_t base = sb + stage * STAGEB;
#pragma unroll
        for (int ks = 0; ks < 2; ks++) {
            uint32_t aH[2][4], aL[2][4];
            const uint32_t acoff = (uint32_t)(((ks * 2 + achb) ^ qA) << 4);
            LDSM4(aH[0], base + (uint32_t)(arow * 64) + acoff);
            LDSM4(aH[1], base + (uint32_t)((arow + 16) * 64) + acoff);
            LDSM4(aL[0], base + AMATB + (uint32_t)(arow * 64) + acoff);
            LDSM4(aL[1], base + AMATB + (uint32_t)((arow + 16) * 64) + acoff);
            const uint32_t bcoff = (uint32_t)(((ks * 2 + bchb) ^ qB) << 4);
#pragma unroll
            for (int p = 0; p < NT / 2; p++) {
                uint32_t bh[4], bl[4];
                LDSM4(bh, base + 2 * AMATB + (uint32_t)((brow + p * 16) * 64) + bcoff);
                LDSM4(bl, base + 2 * AMATB + BMATB + (uint32_t)((brow + p * 16) * 64) + bcoff);
#pragma unroll
                for (int mt = 0; mt < 2; mt++) {
                    MMA_BF16(acc[mt][2 * p],     aH[mt], bh);
                    MMA_BF16(acc[mt][2 * p],     aL[mt], bh);
                    MMA_BF16(acc[mt][2 * p],     aH[mt], bl);
                    MMA_BF16(acc[mt][2 * p + 1], aH[mt], bh + 2);
                    MMA_BF16(acc[mt][2 * p + 1], aL[mt], bh + 2);
                    MMA_BF16(acc[mt][2 * p + 1], aH[mt], bl + 2);
                }
            }
        }
        if (++stage == 3) stage = 0;
    }

#pragma unroll
    for (int mt = 0; mt < 2; mt++) {
        const int row = m0 + wm * 32 + mt * 16 + (lane >> 2);
#pragma unroll
        for (int nt = 0; nt < NT; nt++) {
            const int col = n0 + wn * (BN / 2) + nt * 8 + (lane & 3) * 2;
            *(float2*)&C[(size_t)row * N + col] =
                make_float2(acc[mt][nt][0], acc[mt][nt][1]);
            *(float2*)&C[(size_t)(row + 8) * N + col] =
                make_float2(acc[mt][nt][2], acc[mt][nt][3]);
        }
    }
}
#define GEMMB_SMEM (3 * (2 * 128 * 64 + 2 * 64 * 64))    // 73728

// ---------------- causal depthwise conv (K=4) + SiLU; write u, uT, uH/uL ----------------
__global__ void conv_silu_kernel(const float* __restrict__ cw, const float* __restrict__ cb)
{
    __shared__ float Ts[32][33];
    const int tid = threadIdx.x;                 // 256
    const int m0 = blockIdx.x * 32, d0 = blockIdx.y * 32;
    const int b = m0 >> 10;
    const int l0 = m0 & 1023;
    const int di = tid & 31, lg = tid >> 5;
    const int d = d0 + di;
    const float w0 = cw[d * 4 + 0], w1 = cw[d * 4 + 1];
    const float w2 = cw[d * 4 + 2], w3 = cw[d * 4 + 3];
    const float bias = cb[d];
#pragma unroll
    for (int j = 0; j < 4; j++) {
        const int li = lg * 4 + j;
        const int l = l0 + li;
        const int m = m0 + li;
        float s = bias;
        const float* xcol = g_xz + (size_t)m * (2 * DINNER) + d;
        if (l >= 3) s = fmaf(xcol[-3 * 2 * DINNER], w0, s);
        if (l >= 2) s = fmaf(xcol[-2 * 2 * DINNER], w1, s);
        if (l >= 1) s = fmaf(xcol[-1 * 2 * DINNER], w2, s);
        s = fmaf(xcol[0], w3, s);
        const float uv = siluf(s);
        const size_t o = (size_t)m * DINNER + d;
        g_u[o] = uv;
        __nv_bfloat16 hh = __float2bfloat16(uv);
        g_uH[o] = hh;
        g_uL[o] = __float2bfloat16(uv - __bfloat162float(hh));
        Ts[li][di] = uv;
    }
    __syncthreads();
    const int li2 = tid & 31, dg = tid >> 5;
#pragma unroll
    for (int j = 0; j < 4; j++) {
        const int di2 = dg * 4 + j;
        g_uT[(size_t)(b * DINNER + d0 + di2) * SEQLEN + l0 + li2] = Ts[li2][di2];
    }
}

// ---------------- xdbl pack: sum 8 split-K partials; emit x_dbl + interleaved BC ----------------
__global__ void xdbl_pack_kernel()
{
    const int idx = blockIdx.x * blockDim.x + threadIdx.x;  // < MTOT*24 (float4 over 96 cols)
    const int m = idx / 24, c4 = idx % 24;
    const float4* p = (const float4*)g_xpart;
    const int S = MTOT * NXP128 / 4;   // float4 per slab
    const int o = m * (NXP128 / 4) + c4;
    float4 v = p[o];
#pragma unroll
    for (int k = 1; k < 8; k++) {
        float4 t = p[o + k * S];
        v.x += t.x; v.y += t.y; v.z += t.z; v.w += t.w;
    }
    ((float4*)g_xdbl)[o] = v;
    if (c4 >= 16) {
        const int base = (c4 - 16) * 4;       // 0..28 within BC region (cols 64..95)
        float vv[4] = {v.x, v.y, v.z, v.w};
#pragma unroll
        for (int i = 0; i < 4; i++) {
            const int col = base + i;         // 0..31
            const int off = (col < 16) ? (2 * col) : (2 * (col - 16) + 1);
            g_bc[(size_t)m * 32 + off] = vv[i];
        }
    }
}

// ---------------- delta (transposed): softplus(dt_low @ dt_w^T + 2*dt_b) ----------------
__global__ void dt_delta_kernel(const float* __restrict__ Wd, const float* __restrict__ bd)
{
    __shared__ float XsT[64][68];
    __shared__ float WsT[64][68];
    const int tid = threadIdx.x;                     // 256
    const int m0 = blockIdx.x * 64, d0 = blockIdx.y * 64;
    const int r = tid & 63, cb = tid >> 6;           // cb 0..3
#pragma unroll
    for (int q = 0; q < 4; q++) {
        const int c = cb * 16 + q * 4;
        float4 xv = *(const float4*)(g_xdbl + (size_t)(m0 + r) * NXP128 + c);
        XsT[c + 0][r] = xv.x; XsT[c + 1][r] = xv.y;
        XsT[c + 2][r] = xv.z; XsT[c + 3][r] = xv.w;
        float4 wv = *(const float4*)(Wd + (size_t)(d0 + r) * DTRANK + c);
        WsT[c + 0][r] = wv.x; WsT[c + 1][r] = wv.y;
        WsT[c + 2][r] = wv.z; WsT[c + 3][r] = wv.w;
    }
    __syncthreads();
    const int tx = tid & 15, ty = tid >> 4;
    float acc[4][4];
#pragma unroll
    for (int i = 0; i < 4; i++)
#pragma unroll
        for (int j = 0; j < 4; j++) acc[i][j] = 0.f;
#pragma unroll 8
    for (int k = 0; k < 64; k++) {
        float4 xv = *(const float4*)&XsT[k][ty * 4];
        float4 wv = *(const float4*)&WsT[k][tx * 4];
        float xa[4] = {xv.x, xv.y, xv.z, xv.w};
        float wa[4] = {wv.x, wv.y, wv.z, wv.w};
#pragma unroll
        for (int i = 0; i < 4; i++)
#pragma unroll
            for (int j = 0; j < 4; j++)
                acc[i][j] = fmaf(xa[i], wa[j], acc[i][j]);
    }
    const int b = m0 >> 10;
    const int lb = (m0 & 1023) + ty * 4;
#pragma unroll
    for (int j = 0; j < 4; j++) {
        const int d = d0 + tx * 4 + j;
        const float b2 = 2.f * bd[d];
        float* drow = g_dT + (size_t)(b * DINNER + d) * SEQLEN;
        float sp[4];
#pragma unroll
        for (int i = 0; i < 4; i++) {
            float x = acc[i][j] + b2;
            sp[i] = (x > 20.f) ? x : __logf(1.f + __expf(x));
        }
        *(float4*)(drow + lb) = make_float4(sp[0], sp[1], sp[2], sp[3]);
    }
}

// ---------------- selective scan: lane-per-state, smem deferred reduction ----------------
__global__ __launch_bounds__(64) void scan_kernel(const float* __restrict__ A_log)
{
    __shared__ float P[2][2][16][33];   // [warp][buf][l][g*16+n]
    const int wip = threadIdx.x >> 5;
    const int warp = blockIdx.x * 2 + wip;
    const int lane = threadIdx.x & 31;
    const int b = warp >> 10;
    const int dp = warp & 1023;
    const int g = lane >> 4, n = lane & 15;
    const int d = dp * 2 + g;
    const int ch = b * DINNER + d;
    const float a = -__expf(A_log[d * DSTATE + n]);
    const float* dch = g_dT + (size_t)ch * SEQLEN;
    const float* uch = g_uT + (size_t)ch * SEQLEN;
    const float* bcp = g_bc + (size_t)b * SEQLEN * 32 + 2 * n;
    float* yrow = g_yT + (size_t)ch * SEQLEN;
    float s = 0.f;
    const int pcol = g * 16 + n;
    const int rl = lane & 15, rb = (lane >> 4) * 16;
    for (int l0 = 0; l0 < SEQLEN; l0 += 16) {
        float (*Pb)[33] = P[wip][(l0 >> 4) & 1];
#pragma unroll
        for (int q = 0; q < 4; q++) {
            const int lb = l0 + q * 4;
            float4 dv = *(const float4*)(dch + lb);
            float4 uv = *(const float4*)(uch + lb);
            float dl[4] = {dv.x, dv.y, dv.z, dv.w};
            float uu[4] = {uv.x, uv.y, uv.z, uv.w};
#pragma unroll
            for (int j = 0; j < 4; j++) {
                float2 bcv = *(const float2*)(bcp + (size_t)(lb + j) * 32);
                s = fmaf(__expf(dl[j] * a), s, dl[j] * uu[j] * bcv.x);
                Pb[q * 4 + j][pcol] = s * bcv.y;
            }
        }
        __syncwarp();
        float y = 0.f;
        const float* row = Pb[rl];
#pragma unroll
        for (int k = 0; k < 16; k++) y += row[rb + k];
        yrow[l0 + rl] = y;
    }
}

// ---------------- gating (tiled transpose of yT) + bf16 split ----------------
__global__ void gate_kernel(const float* __restrict__ Dv)
{
    __shared__ float Ts[32][33];
    const int tid = threadIdx.x;                 // 256
    const int m0 = blockIdx.x * 32, d0 = blockIdx.y * 32;
    const int b = m0 >> 10, l0 = m0 & 1023;
    const int lc = tid & 31, drg = tid >> 5;
#pragma unroll
    for (int j = 0; j < 4; j++) {
        const int dr = drg * 4 + j;
        Ts[lc][dr] = g_yT[(size_t)(b * DINNER + d0 + dr) * SEQLEN + l0 + lc];
    }
    __syncthreads();
    const int di = tid & 31, mg = tid >> 5;
    const int d = d0 + di;
    const float dvv = Dv[d];
#pragma unroll
    for (int j = 0; j < 4; j++) {
        const int mi = mg * 4 + j;
        const int m = m0 + mi;
        const float y = Ts[mi][di];
        const float u = g_u[(size_t)m * DINNER + d];
        const float z = g_xz[(size_t)m * (2 * DINNER) + DINNER + d];
        const float v = (y + u * dvv) * siluf(z);
        __nv_bfloat16 hh = __float2bfloat16(v);
        g_y2H[(size_t)m * DINNER + d] = hh;
        g_y2L[(size_t)m * DINNER + d] = __float2bfloat16(v - __bfloat162float(hh));
    }
}

// ---------------- launcher ----------------
extern "C" void kernel_launch(void* const* d_in, const int* in_sizes, int n_in,
                              void* d_out, int out_size)
{
    const float* hs      = (const float*)d_in[0];  // [2,1024,1024]
    const float* inW     = (const float*)d_in[1];  // [4096,1024]
    const float* convW   = (const float*)d_in[2];  // [2048,1,4]
    const float* convB   = (const float*)d_in[3];  // [2048]
    const float* xprojW  = (const float*)d_in[4];  // [96,2048]
    const float* dtW     = (const float*)d_in[5];  // [2048,64]
    const float* dtB     = (const float*)d_in[6];  // [2048]
    const float* A_log   = (const float*)d_in[7];  // [2048,16]
    const float* Dv      = (const float*)d_in[8];  // [2048]
    const float* outW    = (const float*)d_in[9];  // [1024,2048]
    float* out = (float*)d_out;

    float *p_xz, *p_xpart;
    __nv_bfloat16 *p_hsH, *p_hsL, *p_inWH, *p_inWL, *p_uH, *p_uL;
    __nv_bfloat16 *p_xpWH, *p_xpWL, *p_y2H, *p_y2L, *p_outWH, *p_outWL;
    cudaGetSymbolAddress((void**)&p_xz,    g_xz);
    cudaGetSymbolAddress((void**)&p_xpart, g_xpart);
    cudaGetSymbolAddress((void**)&p_hsH,   g_hsH);
    cudaGetSymbolAddress((void**)&p_hsL,   g_hsL);
    cudaGetSymbolAddress((void**)&p_inWH,  g_inWH);
    cudaGetSymbolAddress((void**)&p_inWL,  g_inWL);
    cudaGetSymbolAddress((void**)&p_uH,    g_uH);
    cudaGetSymbolAddress((void**)&p_uL,    g_uL);
    cudaGetSymbolAddress((void**)&p_xpWH,  g_xpWH);
    cudaGetSymbolAddress((void**)&p_xpWL,  g_xpWL);
    cudaGetSymbolAddress((void**)&p_y2H,   g_y2H);
    cudaGetSymbolAddress((void**)&p_y2L,   g_y2L);
    cudaGetSymbolAddress((void**)&p_outWH, g_outWH);
    cudaGetSymbolAddress((void**)&p_outWL, g_outWL);

    static bool attr_set = false;
    if (!attr_set) {
        cudaFuncSetAttribute(mma_gemm64,  cudaFuncAttributeMaxDynamicSharedMemorySize, GEMMB_SMEM);
        cudaFuncSetAttribute(mma_gemm_big, cudaFuncAttributeMaxDynamicSharedMemorySize, GEMMBIG_SMEM);
        attr_set = true;
    }

    // 0) split all four fp32 operands to hi/lo bf16 in ONE launch
    const int n4tot = N4_HS + N4_INW + N4_OUTW + N4_XW;
    split4_kernel<<<(n4tot + 255) / 256, 256>>>(
        hs, p_hsH, p_hsL, inW, p_inWH, p_inWL, outW, p_outWH, p_outWL,
        xprojW, p_xpWH, p_xpWL);

    // 1) xz = hs @ in_proj_w^T (big tile: 64x32 warps, 512 CTAs)
    mma_gemm_big<<<dim3(2 * DINNER / 128, MTOT / 128), 256, GEMMBIG_SMEM>>>(
        p_hsH, p_hsL, p_inWH, p_inWL, p_xz, 2 * DINNER, DMODEL);

    // 2) causal depthwise conv + SiLU -> u, uT, uH/uL
    conv_silu_kernel<<<dim3(MTOT / 32, DINNER / 32), 256>>>(convW, convB);

    // 3) x_dbl = u @ x_proj_w^T (split-K=8 -> 256 CTAs) + pack
    mma_gemm64<<<dim3(NXP128 / 64, MTOT / 128, 8), 256, GEMMB_SMEM>>>(
        p_uH, p_uL, p_xpWH, p_xpWL, p_xpart, NXP128, DINNER, DINNER / 8);
    xdbl_pack_kernel<<<(MTOT * 24) / 256, 256>>>();

    // 4) delta (transposed layout, fast softplus)
    dt_delta_kernel<<<dim3(MTOT / 64, DINNER / 64), 256>>>(dtW, dtB);

    // 5) selective scan (smem deferred reduction, 1024 balanced blocks)
    scan_kernel<<<BATCH * DINNER / 4, 64>>>(A_log);

    // 6) gating + bf16 split (tiled transpose)
    gate_kernel<<<dim3(MTOT / 32, DINNER / 32), 256>>>(Dv);

    // 7) out = y2 @ out_proj_w^T (64-wide: 256 CTAs, ~1 wave)
    mma_gemm64<<<dim3(DMODEL / 64, MTOT / 128, 1), 256, GEMMB_SMEM>>>(
        p_y2H, p_y2L, p_outWH, p_outWL, out, DMODEL, DINNER, DINNER);
}

// round 13
// speedup vs baseline: 1.5348x; 1.5348x over previous
#include <cuda_runtime.h>
#include <cuda_bf16.h>
#include <cuda_fp16.h>
#include <math.h>
#include <stdint.h>

// ---------------- problem constants ----------------
#define BATCH   2
#define SEQLEN  1024
#define DMODEL  1024
#define DINNER  2048
#define DSTATE  16
#define DTRANK  64
#define MTOT    (BATCH*SEQLEN)        // 2048 rows (b*L + l)
#define NXPROJ  96
#define NXP128  128                   // padded x_dbl row stride

// ---------------- scratch (device globals; no allocation) ----------------
__device__ float g_xz   [MTOT * 2*DINNER];  // [m, 4096]  x | z
__device__ float g_u    [MTOT * DINNER];    // [m, d]     conv+silu output
__device__ float g_uT   [BATCH * DINNER * SEQLEN]; // [(b*2048+d), l]
__device__ float g_xdbl [MTOT * NXP128];    // [m, 128]   dt_low | B | C | pad
__device__ float g_xpart[8 * MTOT * NXP128];// split-K fp32 partials
__device__ float g_bc   [MTOT * 32];        // [m][2n]=B_n, [2n+1]=C_n (L2-hot)
__device__ float g_dT   [BATCH * DINNER * SEQLEN]; // delta transposed
__device__ float g_yT   [BATCH * DINNER * SEQLEN]; // scan output [(b*2048+d), l]

// fp16 single-pass GEMM operands
__device__ __half g_hsF  [MTOT * DMODEL];
__device__ __half g_inWF [2*DINNER * DMODEL];
__device__ __half g_outWF[DMODEL * DINNER];
__device__ __half g_y2F  [MTOT * DINNER];
// bf16 hi/lo operands (3-term path for x_dbl)
__device__ __nv_bfloat16 g_uH  [MTOT * DINNER],  g_uL  [MTOT * DINNER];
__device__ __nv_bfloat16 g_xpWH[128 * DINNER],   g_xpWL[128 * DINNER];  // rows 96..127 stay zero

__device__ __forceinline__ float siluf(float x) { return x / (1.f + __expf(-x)); }

// ================= mma helpers (sm_80-compatible PTX) =================
#define MMA_BF16(d, a, b)                                                     \
    asm volatile("mma.sync.aligned.m16n8k16.row.col.f32.bf16.bf16.f32 "       \
        "{%0,%1,%2,%3}, {%4,%5,%6,%7}, {%8,%9}, {%0,%1,%2,%3};"               \
        : "+f"((d)[0]), "+f"((d)[1]), "+f"((d)[2]), "+f"((d)[3])              \
        : "r"((a)[0]), "r"((a)[1]), "r"((a)[2]), "r"((a)[3]),                 \
          "r"((b)[0]), "r"((b)[1]))

#define MMA_F16(d, a, b)                                                      \
    asm volatile("mma.sync.aligned.m16n8k16.row.col.f32.f16.f16.f32 "         \
        "{%0,%1,%2,%3}, {%4,%5,%6,%7}, {%8,%9}, {%0,%1,%2,%3};"               \
        : "+f"((d)[0]), "+f"((d)[1]), "+f"((d)[2]), "+f"((d)[3])              \
        : "r"((a)[0]), "r"((a)[1]), "r"((a)[2]), "r"((a)[3]),                 \
          "r"((b)[0]), "r"((b)[1]))

#define LDSM4(r, addr)                                                        \
    asm volatile("ldmatrix.sync.aligned.m8n8.x4.shared.b16 {%0,%1,%2,%3}, [%4];" \
        : "=r"((r)[0]), "=r"((r)[1]), "=r"((r)[2]), "=r"((r)[3]) : "r"(addr))

#define CP_ASYNC16(s, g)                                                      \
    asm volatile("cp.async.cg.shared.global [%0], [%1], 16;" :: "r"(s), "l"(g))

// byte offset in a [rows x 32 half-words] tile with XOR swizzle (conflict-free)
__device__ __forceinline__ uint32_t swz(int r, int c) {
    return (uint32_t)(r * 64 + ((c ^ ((r >> 1) & 3)) << 4));
}

// ---------------- merged conversion: hs/inW/outW -> fp16, xprojW -> bf16 hi/lo ----------------
#define N4_HS   (MTOT * DMODEL / 4)
#define N4_INW  (2 * DINNER * DMODEL / 4)
#define N4_OUTW (DMODEL * DINNER / 4)
#define N4_XW   (NXPROJ * DINNER / 4)
__global__ void convert_kernel(const float* __restrict__ hs,   __half* __restrict__ hsF,
                               const float* __restrict__ inW,  __half* __restrict__ inWF,
                               const float* __restrict__ outW, __half* __restrict__ outWF,
                               const float* __restrict__ xpW,
                               __nv_bfloat16* __restrict__ xpWH, __nv_bfloat16* __restrict__ xpWL)
{
    int idx = blockIdx.x * blockDim.x + threadIdx.x;   // float4 index
    if (idx < N4_HS + N4_INW + N4_OUTW) {
        const float* s; __half* fp;
        if (idx < N4_HS)               { s = hs;  fp = hsF; }
        else if (idx < N4_HS + N4_INW) { idx -= N4_HS; s = inW; fp = inWF; }
        else                           { idx -= N4_HS + N4_INW; s = outW; fp = outWF; }
        float4 v = ((const float4*)s)[idx];
        union { __half h[4]; uint2 u; } F;
        F.h[0] = __float2half(v.x); F.h[1] = __float2half(v.y);
        F.h[2] = __float2half(v.z); F.h[3] = __float2half(v.w);
        ((uint2*)fp)[idx] = F.u;
    } else {
        idx -= N4_HS + N4_INW + N4_OUTW;
        if (idx >= N4_XW) return;
        float4 v = ((const float4*)xpW)[idx];
        float f[4] = {v.x, v.y, v.z, v.w};
        union { __nv_bfloat16 h[4]; uint2 u; } H, L;
#pragma unroll
        for (int i = 0; i < 4; i++) {
            __nv_bfloat16 hh = __float2bfloat16(f[i]);
            H.h[i] = hh;
            L.h[i] = __float2bfloat16(f[i] - __bfloat162float(hh));
        }
        ((uint2*)xpWH)[idx] = H.u;
        ((uint2*)xpWL)[idx] = L.u;
    }
}

// ---------------- single-pass fp16 MMA GEMM: C[m,n] = A[m,:]·B[n,:] (NT) ----------------
// CTA 128 x 64, BK=32, 8 warps (4m x 2n), 3-stage cp.async ring, 1 barrier/iter.
__global__ __launch_bounds__(256, 3) void mma_gemm_f16(
    const __half* __restrict__ A, const __half* __restrict__ B,
    float* __restrict__ C, int N, int K)
{
    constexpr int BN     = 64;
    constexpr int NT     = BN / 16;           // 4
    constexpr int AMATB  = 128 * 64;          // 8192
    constexpr int BMATB  = BN * 64;           // 4096
    constexpr int STAGEB = AMATB + BMATB;     // 12288

    extern __shared__ __align__(128) char smem[];
    const uint32_t sb = (uint32_t)__cvta_generic_to_shared(smem);
    const int tid = threadIdx.x, lane = tid & 31, wid = tid >> 5;
    const int wm = wid >> 1, wn = wid & 1;
    const int m0 = blockIdx.y * 128, n0 = blockIdx.x * BN;
    const int KT = K >> 5;

    const __half* gA = A + (size_t)m0 * K;
    const __half* gB = B + (size_t)n0 * K;

    const int ar = tid >> 1, ac = (tid & 1) * 2;   // A: 2 chunks/thread
    const int br = tid >> 2, bc = tid & 3;          // B: 1 chunk/thread

    float acc[2][NT][4];
#pragma unroll
    for (int i = 0; i < 2; i++)
#pragma unroll
        for (int j = 0; j < NT; j++)
#pragma unroll
            for (int q = 0; q < 4; q++) acc[i][j][q] = 0.f;

    auto load_tile = [&](int ktIdx, int stage) {
        const int kO = ktIdx * 32;
        const uint32_t sB = sb + stage * STAGEB;
        CP_ASYNC16(sB + swz(ar, ac),     gA + (size_t)ar * K + kO + ac * 8);
        CP_ASYNC16(sB + swz(ar, ac + 1), gA + (size_t)ar * K + kO + ac * 8 + 8);
        CP_ASYNC16(sB + AMATB + swz(br, bc), gB + (size_t)br * K + kO + bc * 8);
        asm volatile("cp.async.commit_group;" ::: "memory");
    };

    load_tile(0, 0);
    load_tile(1, 1);

    const int arow  = wm * 32 + (lane & 15);
    const int achb  = lane >> 4;
    const int qA    = (arow >> 1) & 3;
    const int brow  = wn * (BN / 2) + (lane & 7) + ((lane >> 4) << 3);
    const int bchb  = (lane >> 3) & 1;
    const int qB    = (brow >> 1) & 3;

    int stage = 0;
    for (int kt = 0; kt < KT; kt++) {
        asm volatile("cp.async.wait_group 1;" ::: "memory");
        __syncthreads();
        if (kt + 2 < KT) {
            int ns = stage + 2; if (ns >= 3) ns -= 3;
            load_tile(kt + 2, ns);
        }
        const uint32_t base = sb + stage * STAGEB;
#pragma unroll
        for (int ks = 0; ks < 2; ks++) {
            uint32_t aF[2][4];
            const uint32_t acoff = (uint32_t)(((ks * 2 + achb) ^ qA) << 4);
            LDSM4(aF[0], base + (uint32_t)(arow * 64) + acoff);
            LDSM4(aF[1], base + (uint32_t)((arow + 16) * 64) + acoff);
            const uint32_t bcoff = (uint32_t)(((ks * 2 + bchb) ^ qB) << 4);
#pragma unroll
            for (int p = 0; p < NT / 2; p++) {
                uint32_t bF[4];
                LDSM4(bF, base + AMATB + (uint32_t)((brow + p * 16) * 64) + bcoff);
#pragma unroll
                for (int mt = 0; mt < 2; mt++) {
                    MMA_F16(acc[mt][2 * p],     aF[mt], bF);
                    MMA_F16(acc[mt][2 * p + 1], aF[mt], bF + 2);
                }
            }
        }
        if (++stage == 3) stage = 0;
    }

    // epilogue
#pragma unroll
    for (int mt = 0; mt < 2; mt++) {
        const int row = m0 + wm * 32 + mt * 16 + (lane >> 2);
#pragma unroll
        for (int nt = 0; nt < NT; nt++) {
            const int col = n0 + wn * (BN / 2) + nt * 8 + (lane & 3) * 2;
            *(float2*)&C[(size_t)row * N + col] =
                make_float2(acc[mt][nt][0], acc[mt][nt][1]);
            *(float2*)&C[(size_t)(row + 8) * N + col] =
                make_float2(acc[mt][nt][2], acc[mt][nt][3]);
        }
    }
}
#define GEMMF16_SMEM (3 * (128 * 64 + 64 * 64))   // 36864

// ---------------- 3-term split-bf16 GEMM (x_dbl only): CTA 128x64, split-K via z ----------------
__global__ __launch_bounds__(256, 2) void mma_gemm64(
    const __nv_bfloat16* __restrict__ Ah, const __nv_bfloat16* __restrict__ Al,
    const __nv_bfloat16* __restrict__ Bh, const __nv_bfloat16* __restrict__ Bl,
    float* __restrict__ C, int N, int K, int kLen)
{
    constexpr int BN     = 64;
    constexpr int NT     = BN / 16;           // 4
    constexpr int AMATB  = 128 * 64;          // 8192
    constexpr int BMATB  = BN * 64;           // 4096
    constexpr int STAGEB = 2 * AMATB + 2 * BMATB;   // 24576

    extern __shared__ __align__(128) char smem[];
    const uint32_t sb = (uint32_t)__cvta_generic_to_shared(smem);
    const int tid = threadIdx.x, lane = tid & 31, wid = tid >> 5;
    const int wm = wid >> 1, wn = wid & 1;
    const int m0 = blockIdx.y * 128, n0 = blockIdx.x * BN;
    const int KT = kLen >> 5;
    const int kBase = blockIdx.z * kLen;
    C += (size_t)blockIdx.z * (size_t)(gridDim.y * 128) * N;

    const __nv_bfloat16* gAh = Ah + (size_t)m0 * K + kBase;
    const __nv_bfloat16* gAl = Al + (size_t)m0 * K + kBase;
    const __nv_bfloat16* gBh = Bh + (size_t)n0 * K + kBase;
    const __nv_bfloat16* gBl = Bl + (size_t)n0 * K + kBase;

    const int ar = tid >> 1, ac = (tid & 1) * 2;
    const int br = tid >> 2, bc = tid & 3;

    float acc[2][NT][4];
#pragma unroll
    for (int i = 0; i < 2; i++)
#pragma unroll
        for (int j = 0; j < NT; j++)
#pragma unroll
            for (int q = 0; q < 4; q++) acc[i][j][q] = 0.f;

    auto load_tile = [&](int ktIdx, int stage) {
        const int kO = ktIdx * 32;
        const uint32_t sB = sb + stage * STAGEB;
        CP_ASYNC16(sB + swz(ar, ac),             gAh + (size_t)ar * K + kO + ac * 8);
        CP_ASYNC16(sB + swz(ar, ac + 1),         gAh + (size_t)ar * K + kO + ac * 8 + 8);
        CP_ASYNC16(sB + AMATB + swz(ar, ac),     gAl + (size_t)ar * K + kO + ac * 8);
        CP_ASYNC16(sB + AMATB + swz(ar, ac + 1), gAl + (size_t)ar * K + kO + ac * 8 + 8);
        CP_ASYNC16(sB + 2 * AMATB + swz(br, bc),         gBh + (size_t)br * K + kO + bc * 8);
        CP_ASYNC16(sB + 2 * AMATB + BMATB + swz(br, bc), gBl + (size_t)br * K + kO + bc * 8);
        asm volatile("cp.async.commit_group;" ::: "memory");
    };

    load_tile(0, 0);
    load_tile(1, 1);

    const int arow  = wm * 32 + (lane & 15);
    const int achb  = lane >> 4;
    const int qA    = (arow >> 1) & 3;
    const int brow  = wn * (BN / 2) + (lane & 7) + ((lane >> 4) << 3);
    const int bchb  = (lane >> 3) & 1;
    const int qB    = (brow >> 1) & 3;

    int stage = 0;
    for (int kt = 0; kt < KT; kt++) {
        asm volatile("cp.async.wait_group 1;" ::: "memory");
        __syncthreads();
        if (kt + 2 < KT) {
            int ns = stage + 2; if (ns >= 3) ns -= 3;
            load_tile(kt + 2, ns);
        }
        const uint32_t base = sb + stage * STAGEB;
#pragma unroll
        for (int ks = 0; ks < 2; ks++) {
            uint32_t aH[2][4], aL[2][4];
            const uint32_t acoff = (uint32_t)(((ks * 2 + achb) ^ qA) << 4);
            LDSM4(aH[0], base + (uint32_t)(arow * 64) + acoff);
            LDSM4(aH[1], base + (uint32_t)((arow + 16) * 64) + acoff);
            LDSM4(aL[0], base + AMATB + (uint32_t)(arow * 64) + acoff);
            LDSM4(aL[1], base + AMATB + (uint32_t)((arow + 16) * 64) + acoff);
            const uint32_t bcoff = (uint32_t)(((ks * 2 + bchb) ^ qB) << 4);
#pragma unroll
            for (int p = 0; p < NT / 2; p++) {
                uint32_t bh[4], bl[4];
                LDSM4(bh, base + 2 * AMATB + (uint32_t)((brow + p * 16) * 64) + bcoff);
                LDSM4(bl, base + 2 * AMATB + BMATB + (uint32_t)((brow + p * 16) * 64) + bcoff);
#pragma unroll
                for (int mt = 0; mt < 2; mt++) {
                    MMA_BF16(acc[mt][2 * p],     aH[mt], bh);
                    MMA_BF16(acc[mt][2 * p],     aL[mt], bh);
                    MMA_BF16(acc[mt][2 * p],     aH[mt], bl);
                    MMA_BF16(acc[mt][2 * p + 1], aH[mt], bh + 2);
                    MMA_BF16(acc[mt][2 * p + 1], aL[mt], bh + 2);
                    MMA_BF16(acc[mt][2 * p + 1], aH[mt], bl + 2);
                }
            }
        }
        if (++stage == 3) stage = 0;
    }

#pragma unroll
    for (int mt = 0; mt < 2; mt++) {
        const int row = m0 + wm * 32 + mt * 16 + (lane >> 2);
#pragma unroll
        for (int nt = 0; nt < NT; nt++) {
            const int col = n0 + wn * (BN / 2) + nt * 8 + (lane & 3) * 2;
            *(float2*)&C[(size_t)row * N + col] =
                make_float2(acc[mt][nt][0], acc[mt][nt][1]);
            *(float2*)&C[(size_t)(row + 8) * N + col] =
                make_float2(acc[mt][nt][2], acc[mt][nt][3]);
        }
    }
}
#define GEMMB_SMEM (3 * (2 * 128 * 64 + 2 * 64 * 64))    // 73728

// ---------------- causal depthwise conv (K=4) + SiLU; write u, uT, uH/uL ----------------
__global__ void conv_silu_kernel(const float* __restrict__ cw, const float* __restrict__ cb)
{
    __shared__ float Ts[32][33];
    const int tid = threadIdx.x;                 // 256
    const int m0 = blockIdx.x * 32, d0 = blockIdx.y * 32;
    const int b = m0 >> 10;
    const int l0 = m0 & 1023;
    const int di = tid & 31, lg = tid >> 5;
    const int d = d0 + di;
    const float w0 = cw[d * 4 + 0], w1 = cw[d * 4 + 1];
    const float w2 = cw[d * 4 + 2], w3 = cw[d * 4 + 3];
    const float bias = cb[d];
#pragma unroll
    for (int j = 0; j < 4; j++) {
        const int li = lg * 4 + j;
        const int l = l0 + li;
        const int m = m0 + li;
        float s = bias;
        const float* xcol = g_xz + (size_t)m * (2 * DINNER) + d;
        if (l >= 3) s = fmaf(xcol[-3 * 2 * DINNER], w0, s);
        if (l >= 2) s = fmaf(xcol[-2 * 2 * DINNER], w1, s);
        if (l >= 1) s = fmaf(xcol[-1 * 2 * DINNER], w2, s);
        s = fmaf(xcol[0], w3, s);
        const float uv = siluf(s);
        const size_t o = (size_t)m * DINNER + d;
        g_u[o] = uv;
        __nv_bfloat16 hh = __float2bfloat16(uv);
        g_uH[o] = hh;
        g_uL[o] = __float2bfloat16(uv - __bfloat162float(hh));
        Ts[li][di] = uv;
    }
    __syncthreads();
    const int li2 = tid & 31, dg = tid >> 5;
#pragma unroll
    for (int j = 0; j < 4; j++) {
        const int di2 = dg * 4 + j;
        g_uT[(size_t)(b * DINNER + d0 + di2) * SEQLEN + l0 + li2] = Ts[li2][di2];
    }
}

// ---------------- xdbl pack: sum 8 split-K partials; emit x_dbl + interleaved BC ----------------
__global__ void xdbl_pack_kernel()
{
    const int idx = blockIdx.x * blockDim.x + threadIdx.x;  // < MTOT*24 (float4 over 96 cols)
    const int m = idx / 24, c4 = idx % 24;
    const float4* p = (const float4*)g_xpart;
    const int S = MTOT * NXP128 / 4;   // float4 per slab
    const int o = m * (NXP128 / 4) + c4;
    float4 v = p[o];
#pragma unroll
    for (int k = 1; k < 8; k++) {
        float4 t = p[o + k * S];
        v.x += t.x; v.y += t.y; v.z += t.z; v.w += t.w;
    }
    ((float4*)g_xdbl)[o] = v;
    if (c4 >= 16) {
        const int base = (c4 - 16) * 4;       // 0..28 within BC region (cols 64..95)
        float vv[4] = {v.x, v.y, v.z, v.w};
#pragma unroll
        for (int i = 0; i < 4; i++) {
            const int col = base + i;         // 0..31
            const int off = (col < 16) ? (2 * col) : (2 * (col - 16) + 1);
            g_bc[(size_t)m * 32 + off] = vv[i];
        }
    }
}

// ---------------- delta (transposed): softplus(dt_low @ dt_w^T + 2*dt_b) ----------------
__global__ void dt_delta_kernel(const float* __restrict__ Wd, const float* __restrict__ bd)
{
    __shared__ float XsT[64][68];
    __shared__ float WsT[64][68];
    const int tid = threadIdx.x;                     // 256
    const int m0 = blockIdx.x * 64, d0 = blockIdx.y * 64;
    const int r = tid & 63, cb = tid >> 6;           // cb 0..3
#pragma unroll
    for (int q = 0; q < 4; q++) {
        const int c = cb * 16 + q * 4;
        float4 xv = *(const float4*)(g_xdbl + (size_t)(m0 + r) * NXP128 + c);
        XsT[c + 0][r] = xv.x; XsT[c + 1][r] = xv.y;
        XsT[c + 2][r] = xv.z; XsT[c + 3][r] = xv.w;
        float4 wv = *(const float4*)(Wd + (size_t)(d0 + r) * DTRANK + c);
        WsT[c + 0][r] = wv.x; WsT[c + 1][r] = wv.y;
        WsT[c + 2][r] = wv.z; WsT[c + 3][r] = wv.w;
    }
    __syncthreads();
    const int tx = tid & 15, ty = tid >> 4;
    float acc[4][4];
#pragma unroll
    for (int i = 0; i < 4; i++)
#pragma unroll
        for (int j = 0; j < 4; j++) acc[i][j] = 0.f;
#pragma unroll 8
    for (int k = 0; k < 64; k++) {
        float4 xv = *(const float4*)&XsT[k][ty * 4];
        float4 wv = *(const float4*)&WsT[k][tx * 4];
        float xa[4] = {xv.x, xv.y, xv.z, xv.w};
        float wa[4] = {wv.x, wv.y, wv.z, wv.w};
#pragma unroll
        for (int i = 0; i < 4; i++)
#pragma unroll
            for (int j = 0; j < 4; j++)
                acc[i][j] = fmaf(xa[i], wa[j], acc[i][j]);
    }
    const int b = m0 >> 10;
    const int lb = (m0 & 1023) + ty * 4;
#pragma unroll
    for (int j = 0; j < 4; j++) {
        const int d = d0 + tx * 4 + j;
        const float b2 = 2.f * bd[d];
        float* drow = g_dT + (size_t)(b * DINNER + d) * SEQLEN;
        float sp[4];
#pragma unroll
        for (int i = 0; i < 4; i++) {
            float x = acc[i][j] + b2;
            sp[i] = (x > 20.f) ? x : __logf(1.f + __expf(x));
        }
        *(float4*)(drow + lb) = make_float4(sp[0], sp[1], sp[2], sp[3]);
    }
}

// ---------------- selective scan: lane-per-state, smem deferred reduction ----------------
__global__ __launch_bounds__(64) void scan_kernel(const float* __restrict__ A_log)
{
    __shared__ float P[2][2][16][33];   // [warp][buf][l][g*16+n]
    const int wip = threadIdx.x >> 5;
    const int warp = blockIdx.x * 2 + wip;
    const int lane = threadIdx.x & 31;
    const int b = warp >> 10;
    const int dp = warp & 1023;
    const int g = lane >> 4, n = lane & 15;
    const int d = dp * 2 + g;
    const int ch = b * DINNER + d;
    const float a = -__expf(A_log[d * DSTATE + n]);
    const float* dch = g_dT + (size_t)ch * SEQLEN;
    const float* uch = g_uT + (size_t)ch * SEQLEN;
    const float* bcp = g_bc + (size_t)b * SEQLEN * 32 + 2 * n;
    float* yrow = g_yT + (size_t)ch * SEQLEN;
    float s = 0.f;
    const int pcol = g * 16 + n;
    const int rl = lane & 15, rb = (lane >> 4) * 16;
    for (int l0 = 0; l0 < SEQLEN; l0 += 16) {
        float (*Pb)[33] = P[wip][(l0 >> 4) & 1];
#pragma unroll
        for (int q = 0; q < 4; q++) {
            const int lb = l0 + q * 4;
            float4 dv = *(const float4*)(dch + lb);
            float4 uv = *(const float4*)(uch + lb);
            float dl[4] = {dv.x, dv.y, dv.z, dv.w};
            float uu[4] = {uv.x, uv.y, uv.z, uv.w};
#pragma unroll
            for (int j = 0; j < 4; j++) {
                float2 bcv = *(const float2*)(bcp + (size_t)(lb + j) * 32);
                s = fmaf(__expf(dl[j] * a), s, dl[j] * uu[j] * bcv.x);
                Pb[q * 4 + j][pcol] = s * bcv.y;
            }
        }
        __syncwarp();
        float y = 0.f;
        const float* row = Pb[rl];
#pragma unroll
        for (int k = 0; k < 16; k++) y += row[rb + k];
        yrow[l0 + rl] = y;
    }
}

// ---------------- gating (tiled transpose of yT) -> fp16 y2 ----------------
__global__ void gate_kernel(const float* __restrict__ Dv)
{
    __shared__ float Ts[32][33];
    const int tid = threadIdx.x;                 // 256
    const int m0 = blockIdx.x * 32, d0 = blockIdx.y * 32;
    const int b = m0 >> 10, l0 = m0 & 1023;
    const int lc = tid & 31, drg = tid >> 5;
#pragma unroll
    for (int j = 0; j < 4; j++) {
        const int dr = drg * 4 + j;
        Ts[lc][dr] = g_yT[(size_t)(b * DINNER + d0 + dr) * SEQLEN + l0 + lc];
    }
    __syncthreads();
    const int di = tid & 31, mg = tid >> 5;
    const int d = d0 + di;
    const float dvv = Dv[d];
#pragma unroll
    for (int j = 0; j < 4; j++) {
        const int mi = mg * 4 + j;
        const int m = m0 + mi;
        const float y = Ts[mi][di];
        const float u = g_u[(size_t)m * DINNER + d];
        const float z = g_xz[(size_t)m * (2 * DINNER) + DINNER + d];
        const float v = (y + u * dvv) * siluf(z);
        g_y2F[(size_t)m * DINNER + d] = __float2half(v);
    }
}

// ---------------- launcher ----------------
extern "C" void kernel_launch(void* const* d_in, const int* in_sizes, int n_in,
                              void* d_out, int out_size)
{
    const float* hs      = (const float*)d_in[0];  // [2,1024,1024]
    const float* inW     = (const float*)d_in[1];  // [4096,1024]
    const float* convW   = (const float*)d_in[2];  // [2048,1,4]
    const float* convB   = (const float*)d_in[3];  // [2048]
    const float* xprojW  = (const float*)d_in[4];  // [96,2048]
    const float* dtW     = (const float*)d_in[5];  // [2048,64]
    const float* dtB     = (const float*)d_in[6];  // [2048]
    const float* A_log   = (const float*)d_in[7];  // [2048,16]
    const float* Dv      = (const float*)d_in[8];  // [2048]
    const float* outW    = (const float*)d_in[9];  // [1024,2048]
    float* out = (float*)d_out;

    float *p_xz, *p_xpart;
    __half *p_hsF, *p_inWF, *p_outWF, *p_y2F;
    __nv_bfloat16 *p_uH, *p_uL, *p_xpWH, *p_xpWL;
    cudaGetSymbolAddress((void**)&p_xz,    g_xz);
    cudaGetSymbolAddress((void**)&p_xpart, g_xpart);
    cudaGetSymbolAddress((void**)&p_hsF,   g_hsF);
    cudaGetSymbolAddress((void**)&p_inWF,  g_inWF);
    cudaGetSymbolAddress((void**)&p_outWF, g_outWF);
    cudaGetSymbolAddress((void**)&p_y2F,   g_y2F);
    cudaGetSymbolAddress((void**)&p_uH,    g_uH);
    cudaGetSymbolAddress((void**)&p_uL,    g_uL);
    cudaGetSymbolAddress((void**)&p_xpWH,  g_xpWH);
    cudaGetSymbolAddress((void**)&p_xpWL,  g_xpWL);

    static bool attr_set = false;
    if (!attr_set) {
        cudaFuncSetAttribute(mma_gemm64,   cudaFuncAttributeMaxDynamicSharedMemorySize, GEMMB_SMEM);
        cudaFuncSetAttribute(mma_gemm_f16, cudaFuncAttributeMaxDynamicSharedMemorySize, GEMMF16_SMEM);
        attr_set = true;
    }

    // 0) convert operands: hs/inW/outW -> fp16, xprojW -> bf16 hi/lo
    const int n4tot = N4_HS + N4_INW + N4_OUTW + N4_XW;
    convert_kernel<<<(n4tot + 255) / 256, 256>>>(
        hs, p_hsF, inW, p_inWF, outW, p_outWF, xprojW, p_xpWH, p_xpWL);

    // 1) xz = hs @ in_proj_w^T (fp16 single-pass, 1024 CTAs)
    mma_gemm_f16<<<dim3(2 * DINNER / 64, MTOT / 128), 256, GEMMF16_SMEM>>>(
        p_hsF, p_inWF, p_xz, 2 * DINNER, DMODEL);

    // 2) causal depthwise conv + SiLU -> u, uT, uH/uL
    conv_silu_kernel<<<dim3(MTOT / 32, DINNER / 32), 256>>>(convW, convB);

    // 3) x_dbl = u @ x_proj_w^T (3-term bf16, split-K=8 -> 256 CTAs) + pack
    mma_gemm64<<<dim3(NXP128 / 64, MTOT / 128, 8), 256, GEMMB_SMEM>>>(
        p_uH, p_uL, p_xpWH, p_xpWL, p_xpart, NXP128, DINNER, DINNER / 8);
    xdbl_pack_kernel<<<(MTOT * 24) / 256, 256>>>();

    // 4) delta (transposed layout, fast softplus)
    dt_delta_kernel<<<dim3(MTOT / 64, DINNER / 64), 256>>>(dtW, dtB);

    // 5) selective scan (smem deferred reduction, 1024 balanced blocks)
    scan_kernel<<<BATCH * DINNER / 4, 64>>>(A_log);

    // 6) gating -> fp16 y2 (tiled transpose)
    gate_kernel<<<dim3(MTOT / 32, DINNER / 32), 256>>>(Dv);

    // 7) out = y2 @ out_proj_w^T (fp16 single-pass, 256 CTAs)
    mma_gemm_f16<<<dim3(DMODEL / 64, MTOT / 128), 256, GEMMF16_SMEM>>>(
        p_y2F, p_outWF, out, DMODEL, DINNER);
}

// round 14
// speedup vs baseline: 1.6198x; 1.0554x over previous
#include <cuda_runtime.h>
#include <cuda_fp16.h>
#include <math.h>
#include <stdint.h>

// ---------------- problem constants ----------------
#define BATCH   2
#define SEQLEN  1024
#define DMODEL  1024
#define DINNER  2048
#define DSTATE  16
#define DTRANK  64
#define MTOT    (BATCH*SEQLEN)        // 2048 rows (b*L + l)
#define NXPROJ  96
#define NXP128  128                   // padded x_dbl row stride

// ---------------- scratch (device globals; no allocation) ----------------
__device__ float g_xz   [MTOT * 2*DINNER];  // [m, 4096]  x | z
__device__ float g_u    [MTOT * DINNER];    // [m, d]     conv+silu output
__device__ float g_uT   [BATCH * DINNER * SEQLEN]; // [(b*2048+d), l]
__device__ float g_xdbl [MTOT * NXP128];    // [m, 128]   dt_low | B | C | pad
__device__ float g_xpart[8 * MTOT * NXP128];// split-K fp32 partials
__device__ float g_bc   [MTOT * 32];        // [m][2n]=B_n, [2n+1]=C_n (L2-hot)
__device__ float g_dT   [BATCH * DINNER * SEQLEN]; // delta transposed
__device__ float g_yT   [BATCH * DINNER * SEQLEN]; // scan output [(b*2048+d), l]

// fp16 GEMM operands
__device__ __half g_hsF  [MTOT * DMODEL];
__device__ __half g_inWF [2*DINNER * DMODEL];
__device__ __half g_outWF[DMODEL * DINNER];
__device__ __half g_y2F  [MTOT * DINNER];
__device__ __half g_uF   [MTOT * DINNER];
__device__ __half g_xpWF [128 * DINNER];    // rows 96..127 stay zero

__device__ __forceinline__ float siluf(float x) { return x / (1.f + __expf(-x)); }

// ================= mma helpers (sm_80-compatible PTX) =================
#define MMA_F16(d, a, b)                                                      \
    asm volatile("mma.sync.aligned.m16n8k16.row.col.f32.f16.f16.f32 "         \
        "{%0,%1,%2,%3}, {%4,%5,%6,%7}, {%8,%9}, {%0,%1,%2,%3};"               \
        : "+f"((d)[0]), "+f"((d)[1]), "+f"((d)[2]), "+f"((d)[3])              \
        : "r"((a)[0]), "r"((a)[1]), "r"((a)[2]), "r"((a)[3]),                 \
          "r"((b)[0]), "r"((b)[1]))

#define LDSM4(r, addr)                                                        \
    asm volatile("ldmatrix.sync.aligned.m8n8.x4.shared.b16 {%0,%1,%2,%3}, [%4];" \
        : "=r"((r)[0]), "=r"((r)[1]), "=r"((r)[2]), "=r"((r)[3]) : "r"(addr))

#define CP_ASYNC16(s, g)                                                      \
    asm volatile("cp.async.cg.shared.global [%0], [%1], 16;" :: "r"(s), "l"(g))

// byte offset in a [rows x 32 half-words] tile with XOR swizzle (conflict-free)
__device__ __forceinline__ uint32_t swz(int r, int c) {
    return (uint32_t)(r * 64 + ((c ^ ((r >> 1) & 3)) << 4));
}

// ---------------- merged conversion: hs/inW/outW/xprojW -> fp16 ----------------
#define N4_HS   (MTOT * DMODEL / 4)
#define N4_INW  (2 * DINNER * DMODEL / 4)
#define N4_OUTW (DMODEL * DINNER / 4)
#define N4_XW   (NXPROJ * DINNER / 4)
__global__ void convert_kernel(const float* __restrict__ hs,   __half* __restrict__ hsF,
                               const float* __restrict__ inW,  __half* __restrict__ inWF,
                               const float* __restrict__ outW, __half* __restrict__ outWF,
                               const float* __restrict__ xpW,  __half* __restrict__ xpWF)
{
    int idx = blockIdx.x * blockDim.x + threadIdx.x;   // float4 index
    if (idx >= N4_HS + N4_INW + N4_OUTW + N4_XW) return;
    const float* s; __half* fp;
    if (idx < N4_HS)                          { s = hs;  fp = hsF; }
    else if (idx < N4_HS + N4_INW)            { idx -= N4_HS; s = inW; fp = inWF; }
    else if (idx < N4_HS + N4_INW + N4_OUTW)  { idx -= N4_HS + N4_INW; s = outW; fp = outWF; }
    else                                      { idx -= N4_HS + N4_INW + N4_OUTW; s = xpW; fp = xpWF; }
    float4 v = ((const float4*)s)[idx];
    union { __half h[4]; uint2 u; } F;
    F.h[0] = __float2half(v.x); F.h[1] = __float2half(v.y);
    F.h[2] = __float2half(v.z); F.h[3] = __float2half(v.w);
    ((uint2*)fp)[idx] = F.u;
}

// ---------------- single-pass fp16 MMA GEMM: C[m,n] = A[m,:]·B[n,:] (NT) ----------------
// CTA 128 x 64, BK=32, 8 warps (4m x 2n), 3-stage cp.async ring, 1 barrier/iter.
// Optional split-K via blockIdx.z: each z handles kLen columns -> its own C slab.
__global__ __launch_bounds__(256, 3) void mma_gemm_f16(
    const __half* __restrict__ A, const __half* __restrict__ B,
    float* __restrict__ C, int N, int K, int kLen)
{
    constexpr int BN     = 64;
    constexpr int NT     = BN / 16;           // 4
    constexpr int AMATB  = 128 * 64;          // 8192
    constexpr int BMATB  = BN * 64;           // 4096
    constexpr int STAGEB = AMATB + BMATB;     // 12288

    extern __shared__ __align__(128) char smem[];
    const uint32_t sb = (uint32_t)__cvta_generic_to_shared(smem);
    const int tid = threadIdx.x, lane = tid & 31, wid = tid >> 5;
    const int wm = wid >> 1, wn = wid & 1;
    const int m0 = blockIdx.y * 128, n0 = blockIdx.x * BN;
    const int KT = kLen >> 5;
    const int kBase = blockIdx.z * kLen;
    C += (size_t)blockIdx.z * (size_t)(gridDim.y * 128) * N;

    const __half* gA = A + (size_t)m0 * K + kBase;
    const __half* gB = B + (size_t)n0 * K + kBase;

    const int ar = tid >> 1, ac = (tid & 1) * 2;   // A: 2 chunks/thread
    const int br = tid >> 2, bc = tid & 3;          // B: 1 chunk/thread

    float acc[2][NT][4];
#pragma unroll
    for (int i = 0; i < 2; i++)
#pragma unroll
        for (int j = 0; j < NT; j++)
#pragma unroll
            for (int q = 0; q < 4; q++) acc[i][j][q] = 0.f;

    auto load_tile = [&](int ktIdx, int stage) {
        const int kO = ktIdx * 32;
        const uint32_t sB = sb + stage * STAGEB;
        CP_ASYNC16(sB + swz(ar, ac),     gA + (size_t)ar * K + kO + ac * 8);
        CP_ASYNC16(sB + swz(ar, ac + 1), gA + (size_t)ar * K + kO + ac * 8 + 8);
        CP_ASYNC16(sB + AMATB + swz(br, bc), gB + (size_t)br * K + kO + bc * 8);
        asm volatile("cp.async.commit_group;" ::: "memory");
    };

    load_tile(0, 0);
    load_tile(1, 1);

    const int arow  = wm * 32 + (lane & 15);
    const int achb  = lane >> 4;
    const int qA    = (arow >> 1) & 3;
    const int brow  = wn * (BN / 2) + (lane & 7) + ((lane >> 4) << 3);
    const int bchb  = (lane >> 3) & 1;
    const int qB    = (brow >> 1) & 3;

    int stage = 0;
    for (int kt = 0; kt < KT; kt++) {
        asm volatile("cp.async.wait_group 1;" ::: "memory");
        __syncthreads();
        if (kt + 2 < KT) {
            int ns = stage + 2; if (ns >= 3) ns -= 3;
            load_tile(kt + 2, ns);
        }
        const uint32_t base = sb + stage * STAGEB;
#pragma unroll
        for (int ks = 0; ks < 2; ks++) {
            uint32_t aF[2][4];
            const uint32_t acoff = (uint32_t)(((ks * 2 + achb) ^ qA) << 4);
            LDSM4(aF[0], base + (uint32_t)(arow * 64) + acoff);
            LDSM4(aF[1], base + (uint32_t)((arow + 16) * 64) + acoff);
            const uint32_t bcoff = (uint32_t)(((ks * 2 + bchb) ^ qB) << 4);
#pragma unroll
            for (int p = 0; p < NT / 2; p++) {
                uint32_t bF[4];
                LDSM4(bF, base + AMATB + (uint32_t)((brow + p * 16) * 64) + bcoff);
#pragma unroll
                for (int mt = 0; mt < 2; mt++) {
                    MMA_F16(acc[mt][2 * p],     aF[mt], bF);
                    MMA_F16(acc[mt][2 * p + 1], aF[mt], bF + 2);
                }
            }
        }
        if (++stage == 3) stage = 0;
    }

    // epilogue
#pragma unroll
    for (int mt = 0; mt < 2; mt++) {
        const int row = m0 + wm * 32 + mt * 16 + (lane >> 2);
#pragma unroll
        for (int nt = 0; nt < NT; nt++) {
            const int col = n0 + wn * (BN / 2) + nt * 8 + (lane & 3) * 2;
            *(float2*)&C[(size_t)row * N + col] =
                make_float2(acc[mt][nt][0], acc[mt][nt][1]);
            *(float2*)&C[(size_t)(row + 8) * N + col] =
                make_float2(acc[mt][nt][2], acc[mt][nt][3]);
        }
    }
}
#define GEMMF16_SMEM (3 * (128 * 64 + 64 * 64))   // 36864

// ---------------- causal depthwise conv (K=4) + SiLU; write u, uT, uF ----------------
__global__ void conv_silu_kernel(const float* __restrict__ cw, const float* __restrict__ cb)
{
    __shared__ float Ts[32][33];
    const int tid = threadIdx.x;                 // 256
    const int m0 = blockIdx.x * 32, d0 = blockIdx.y * 32;
    const int b = m0 >> 10;
    const int l0 = m0 & 1023;
    const int di = tid & 31, lg = tid >> 5;
    const int d = d0 + di;
    const float w0 = cw[d * 4 + 0], w1 = cw[d * 4 + 1];
    const float w2 = cw[d * 4 + 2], w3 = cw[d * 4 + 3];
    const float bias = cb[d];
#pragma unroll
    for (int j = 0; j < 4; j++) {
        const int li = lg * 4 + j;
        const int l = l0 + li;
        const int m = m0 + li;
        float s = bias;
        const float* xcol = g_xz + (size_t)m * (2 * DINNER) + d;
        if (l >= 3) s = fmaf(xcol[-3 * 2 * DINNER], w0, s);
        if (l >= 2) s = fmaf(xcol[-2 * 2 * DINNER], w1, s);
        if (l >= 1) s = fmaf(xcol[-1 * 2 * DINNER], w2, s);
        s = fmaf(xcol[0], w3, s);
        const float uv = siluf(s);
        const size_t o = (size_t)m * DINNER + d;
        g_u[o] = uv;
        g_uF[o] = __float2half(uv);
        Ts[li][di] = uv;
    }
    __syncthreads();
    const int li2 = tid & 31, dg = tid >> 5;
#pragma unroll
    for (int j = 0; j < 4; j++) {
        const int di2 = dg * 4 + j;
        g_uT[(size_t)(b * DINNER + d0 + di2) * SEQLEN + l0 + li2] = Ts[li2][di2];
    }
}

// ---------------- xdbl pack: sum 8 split-K partials; emit x_dbl + interleaved BC ----------------
__global__ void xdbl_pack_kernel()
{
    const int idx = blockIdx.x * blockDim.x + threadIdx.x;  // < MTOT*24 (float4 over 96 cols)
    const int m = idx / 24, c4 = idx % 24;
    const float4* p = (const float4*)g_xpart;
    const int S = MTOT * NXP128 / 4;   // float4 per slab
    const int o = m * (NXP128 / 4) + c4;
    float4 v = p[o];
#pragma unroll
    for (int k = 1; k < 8; k++) {
        float4 t = p[o + k * S];
        v.x += t.x; v.y += t.y; v.z += t.z; v.w += t.w;
    }
    ((float4*)g_xdbl)[o] = v;
    if (c4 >= 16) {
        const int base = (c4 - 16) * 4;       // 0..28 within BC region (cols 64..95)
        float vv[4] = {v.x, v.y, v.z, v.w};
#pragma unroll
        for (int i = 0; i < 4; i++) {
            const int col = base + i;         // 0..31
            const int off = (col < 16) ? (2 * col) : (2 * (col - 16) + 1);
            g_bc[(size_t)m * 32 + off] = vv[i];
        }
    }
}

// ---------------- delta (transposed): softplus(dt_low @ dt_w^T + 2*dt_b) ----------------
__global__ void dt_delta_kernel(const float* __restrict__ Wd, const float* __restrict__ bd)
{
    __shared__ float XsT[64][68];
    __shared__ float WsT[64][68];
    const int tid = threadIdx.x;                     // 256
    const int m0 = blockIdx.x * 64, d0 = blockIdx.y * 64;
    const int r = tid & 63, cb = tid >> 6;           // cb 0..3
#pragma unroll
    for (int q = 0; q < 4; q++) {
        const int c = cb * 16 + q * 4;
        float4 xv = *(const float4*)(g_xdbl + (size_t)(m0 + r) * NXP128 + c);
        XsT[c + 0][r] = xv.x; XsT[c + 1][r] = xv.y;
        XsT[c + 2][r] = xv.z; XsT[c + 3][r] = xv.w;
        float4 wv = *(const float4*)(Wd + (size_t)(d0 + r) * DTRANK + c);
        WsT[c + 0][r] = wv.x; WsT[c + 1][r] = wv.y;
        WsT[c + 2][r] = wv.z; WsT[c + 3][r] = wv.w;
    }
    __syncthreads();
    const int tx = tid & 15, ty = tid >> 4;
    float acc[4][4];
#pragma unroll
    for (int i = 0; i < 4; i++)
#pragma unroll
        for (int j = 0; j < 4; j++) acc[i][j] = 0.f;
#pragma unroll 8
    for (int k = 0; k < 64; k++) {
        float4 xv = *(const float4*)&XsT[k][ty * 4];
        float4 wv = *(const float4*)&WsT[k][tx * 4];
        float xa[4] = {xv.x, xv.y, xv.z, xv.w};
        float wa[4] = {wv.x, wv.y, wv.z, wv.w};
#pragma unroll
        for (int i = 0; i < 4; i++)
#pragma unroll
            for (int j = 0; j < 4; j++)
                acc[i][j] = fmaf(xa[i], wa[j], acc[i][j]);
    }
    const int b = m0 >> 10;
    const int lb = (m0 & 1023) + ty * 4;
#pragma unroll
    for (int j = 0; j < 4; j++) {
        const int d = d0 + tx * 4 + j;
        const float b2 = 2.f * bd[d];
        float* drow = g_dT + (size_t)(b * DINNER + d) * SEQLEN;
        float sp[4];
#pragma unroll
        for (int i = 0; i < 4; i++) {
            float x = acc[i][j] + b2;
            sp[i] = (x > 20.f) ? x : __logf(1.f + __expf(x));
        }
        *(float4*)(drow + lb) = make_float4(sp[0], sp[1], sp[2], sp[3]);
    }
}

// ---------------- selective scan: lane-per-state, smem deferred reduction ----------------
__global__ __launch_bounds__(64) void scan_kernel(const float* __restrict__ A_log)
{
    __shared__ float P[2][2][16][33];   // [warp][buf][l][g*16+n]
    const int wip = threadIdx.x >> 5;
    const int warp = blockIdx.x * 2 + wip;
    const int lane = threadIdx.x & 31;
    const int b = warp >> 10;
    const int dp = warp & 1023;
    const int g = lane >> 4, n = lane & 15;
    const int d = dp * 2 + g;
    const int ch = b * DINNER + d;
    const float a = -__expf(A_log[d * DSTATE + n]);
    const float* dch = g_dT + (size_t)ch * SEQLEN;
    const float* uch = g_uT + (size_t)ch * SEQLEN;
    const float* bcp = g_bc + (size_t)b * SEQLEN * 32 + 2 * n;
    float* yrow = g_yT + (size_t)ch * SEQLEN;
    float s = 0.f;
    const int pcol = g * 16 + n;
    const int rl = lane & 15, rb = (lane >> 4) * 16;
    for (int l0 = 0; l0 < SEQLEN; l0 += 16) {
        float (*Pb)[33] = P[wip][(l0 >> 4) & 1];
#pragma unroll
        for (int q = 0; q < 4; q++) {
            const int lb = l0 + q * 4;
            float4 dv = *(const float4*)(dch + lb);
            float4 uv = *(const float4*)(uch + lb);
            float dl[4] = {dv.x, dv.y, dv.z, dv.w};
            float uu[4] = {uv.x, uv.y, uv.z, uv.w};
#pragma unroll
            for (int j = 0; j < 4; j++) {
                float2 bcv = *(const float2*)(bcp + (size_t)(lb + j) * 32);
                s = fmaf(__expf(dl[j] * a), s, dl[j] * uu[j] * bcv.x);
                Pb[q * 4 + j][pcol] = s * bcv.y;
            }
        }
        __syncwarp();
        float y = 0.f;
        const float* row = Pb[rl];
#pragma unroll
        for (int k = 0; k < 16; k++) y += row[rb + k];
        yrow[l0 + rl] = y;
    }
}

// ---------------- gating (tiled transpose of yT) -> fp16 y2 ----------------
__global__ void gate_kernel(const float* __restrict__ Dv)
{
    __shared__ float Ts[32][33];
    const int tid = threadIdx.x;                 // 256
    const int m0 = blockIdx.x * 32, d0 = blockIdx.y * 32;
    const int b = m0 >> 10, l0 = m0 & 1023;
    const int lc = tid & 31, drg = tid >> 5;
#pragma unroll
    for (int j = 0; j < 4; j++) {
        const int dr = drg * 4 + j;
        Ts[lc][dr] = g_yT[(size_t)(b * DINNER + d0 + dr) * SEQLEN + l0 + lc];
    }
    __syncthreads();
    const int di = tid & 31, mg = tid >> 5;
    const int d = d0 + di;
    const float dvv = Dv[d];
#pragma unroll
    for (int j = 0; j < 4; j++) {
        const int mi = mg * 4 + j;
        const int m = m0 + mi;
        const float y = Ts[mi][di];
        const float u = g_u[(size_t)m * DINNER + d];
        const float z = g_xz[(size_t)m * (2 * DINNER) + DINNER + d];
        const float v = (y + u * dvv) * siluf(z);
        g_y2F[(size_t)m * DINNER + d] = __float2half(v);
    }
}

// ---------------- launcher ----------------
extern "C" void kernel_launch(void* const* d_in, const int* in_sizes, int n_in,
                              void* d_out, int out_size)
{
    const float* hs      = (const float*)d_in[0];  // [2,1024,1024]
    const float* inW     = (const float*)d_in[1];  // [4096,1024]
    const float* convW   = (const float*)d_in[2];  // [2048,1,4]
    const float* convB   = (const float*)d_in[3];  // [2048]
    const float* xprojW  = (const float*)d_in[4];  // [96,2048]
    const float* dtW     = (const float*)d_in[5];  // [2048,64]
    const float* dtB     = (const float*)d_in[6];  // [2048]
    const float* A_log   = (const float*)d_in[7];  // [2048,16]
    const float* Dv      = (const float*)d_in[8];  // [2048]
    const float* outW    = (const float*)d_in[9];  // [1024,2048]
    float* out = (float*)d_out;

    float *p_xz, *p_xpart;
    __half *p_hsF, *p_inWF, *p_outWF, *p_y2F, *p_uF, *p_xpWF;
    cudaGetSymbolAddress((void**)&p_xz,    g_xz);
    cudaGetSymbolAddress((void**)&p_xpart, g_xpart);
    cudaGetSymbolAddress((void**)&p_hsF,   g_hsF);
    cudaGetSymbolAddress((void**)&p_inWF,  g_inWF);
    cudaGetSymbolAddress((void**)&p_outWF, g_outWF);
    cudaGetSymbolAddress((void**)&p_y2F,   g_y2F);
    cudaGetSymbolAddress((void**)&p_uF,    g_uF);
    cudaGetSymbolAddress((void**)&p_xpWF,  g_xpWF);

    static bool attr_set = false;
    if (!attr_set) {
        cudaFuncSetAttribute(mma_gemm_f16, cudaFuncAttributeMaxDynamicSharedMemorySize, GEMMF16_SMEM);
        attr_set = true;
    }

    // 0) convert all fp32 operands to fp16 in ONE launch
    const int n4tot = N4_HS + N4_INW + N4_OUTW + N4_XW;
    convert_kernel<<<(n4tot + 255) / 256, 256>>>(
        hs, p_hsF, inW, p_inWF, outW, p_outWF, xprojW, p_xpWF);

    // 1) xz = hs @ in_proj_w^T (fp16, 1024 CTAs)
    mma_gemm_f16<<<dim3(2 * DINNER / 64, MTOT / 128, 1), 256, GEMMF16_SMEM>>>(
        p_hsF, p_inWF, p_xz, 2 * DINNER, DMODEL, DMODEL);

    // 2) causal depthwise conv + SiLU -> u, uT, uF
    conv_silu_kernel<<<dim3(MTOT / 32, DINNER / 32), 256>>>(convW, convB);

    // 3) x_dbl = u @ x_proj_w^T (fp16, split-K=8 -> 256 CTAs) + pack
    mma_gemm_f16<<<dim3(NXP128 / 64, MTOT / 128, 8), 256, GEMMF16_SMEM>>>(
        p_uF, p_xpWF, p_xpart, NXP128, DINNER, DINNER / 8);
    xdbl_pack_kernel<<<(MTOT * 24) / 256, 256>>>();

    // 4) delta (transposed layout, fast softplus)
    dt_delta_kernel<<<dim3(MTOT / 64, DINNER / 64), 256>>>(dtW, dtB);

    // 5) selective scan (smem deferred reduction, 1024 balanced blocks)
    scan_kernel<<<BATCH * DINNER / 4, 64>>>(A_log);

    // 6) gating -> fp16 y2 (tiled transpose)
    gate_kernel<<<dim3(MTOT / 32, DINNER / 32), 256>>>(Dv);

    // 7) out = y2 @ out_proj_w^T (fp16, 256 CTAs)
    mma_gemm_f16<<<dim3(DMODEL / 64, MTOT / 128, 1), 256, GEMMF16_SMEM>>>(
        p_y2F, p_outWF, out, DMODEL, DINNER, DINNER);
}